// round 7
// baseline (speedup 1.0000x reference)
#include <cuda_runtime.h>
#include <cuda_bf16.h>

#define RANK     64
#define WINDOW   11
#define PADR     5
#define TILE     64
#define NTHREADS 256
#define NWARPS   8
#define ROWS_PER_WARP (TILE / NWARPS)   // 8
#define XROWS    (TILE + 2 * PADR)      // 74
#define WPITCH   76                     // floats per staged-W row; lane*19 mod 8 distinct -> conflict-free float4 LDS

__global__ __launch_bounds__(NTHREADS, 1)
void attn_win_kernel(const float* __restrict__ X,
                     const float* __restrict__ W,
                     const float* __restrict__ bvec,
                     float* __restrict__ out,
                     int L)
{
    __shared__ float xs[XROWS * RANK];     // 18944 B
    __shared__ float ws[RANK * WPITCH];    // 19456 B

    const int tid  = threadIdx.x;
    const int lane = tid & 31;
    const int warp = tid >> 5;
    const int base = blockIdx.x * TILE;

    // ---- stage X tile (zero-padded at global edges), coalesced float4 ----
    {
        const float4* X4  = reinterpret_cast<const float4*>(X);
        float4*       xs4 = reinterpret_cast<float4*>(xs);
        #pragma unroll 2
        for (int idx = tid; idx < XROWS * (RANK / 4); idx += NTHREADS) {
            int i  = idx >> 4;        // tile row (16 float4 chunks per row)
            int ch = idx & 15;
            int g  = base + i - PADR;
            float4 v = make_float4(0.f, 0.f, 0.f, 0.f);
            if (g >= 0 && g < L) v = X4[g * (RANK / 4) + ch];
            xs4[i * (RANK / 4) + ch] = v;
        }
    }
    // ---- stage W into padded-pitch SMEM (once per block) ----
    {
        const float4* W4 = reinterpret_cast<const float4*>(W);
        for (int idx = tid; idx < RANK * (RANK / 4); idx += NTHREADS) {
            int r  = idx >> 4;
            int ch = idx & 15;
            float4 v = W4[idx];
            *reinterpret_cast<float4*>(&ws[r * WPITCH + ch * 4]) = v;
        }
    }
    __syncthreads();

    // ---- per-lane channels: c0 = lane, c1 = lane+32; W rows held in registers ----
    const int c0 = lane;
    const int c1 = lane + 32;
    float w0[RANK], w1[RANK];
    #pragma unroll
    for (int j = 0; j < RANK / 4; j++) {
        float4 a = *reinterpret_cast<const float4*>(&ws[c0 * WPITCH + j * 4]);
        w0[4*j+0] = a.x; w0[4*j+1] = a.y; w0[4*j+2] = a.z; w0[4*j+3] = a.w;
        float4 c = *reinterpret_cast<const float4*>(&ws[c1 * WPITCH + j * 4]);
        w1[4*j+0] = c.x; w1[4*j+1] = c.y; w1[4*j+2] = c.z; w1[4*j+3] = c.w;
    }
    const float bias0 = bvec[c0];
    const float bias1 = bvec[c1];

    for (int rr = 0; rr < ROWS_PER_WARP; rr++) {
        const int lr = warp * ROWS_PER_WARP + rr;
        const int g  = base + lr;
        if (g >= L) break;   // uniform per warp

        // ---- GEMV: v = tanh(x[g] @ W^T + b) for channels c0, c1 ----
        float acc0 = bias0, acc1 = bias1;
        const float4* xr4 = reinterpret_cast<const float4*>(&xs[(lr + PADR) * RANK]);
        #pragma unroll
        for (int j = 0; j < RANK / 4; j++) {
            float4 xv = xr4[j];                     // broadcast LDS.128
            acc0 = fmaf(xv.x, w0[4*j+0], acc0);
            acc0 = fmaf(xv.y, w0[4*j+1], acc0);
            acc0 = fmaf(xv.z, w0[4*j+2], acc0);
            acc0 = fmaf(xv.w, w0[4*j+3], acc0);
            acc1 = fmaf(xv.x, w1[4*j+0], acc1);
            acc1 = fmaf(xv.y, w1[4*j+1], acc1);
            acc1 = fmaf(xv.z, w1[4*j+2], acc1);
            acc1 = fmaf(xv.w, w1[4*j+3], acc1);
        }
        const float v0 = tanhf(acc0);
        const float v1 = tanhf(acc1);

        // ---- window scores: s[w] = <x[g+w-5], v> / 8 ----
        float xw0[WINDOW], xw1[WINDOW], s[WINDOW];
        #pragma unroll
        for (int w = 0; w < WINDOW; w++) {
            xw0[w] = xs[(lr + w) * RANK + c0];
            xw1[w] = xs[(lr + w) * RANK + c1];
            float p = xw0[w] * v0 + xw1[w] * v1;
            #pragma unroll
            for (int o = 16; o > 0; o >>= 1)
                p += __shfl_xor_sync(0xffffffffu, p, o);
            s[w] = p * 0.125f;   // 1/sqrt(RANK)
        }

        // ---- softmax over the window (all lanes redundantly, in registers) ----
        float m = s[0];
        #pragma unroll
        for (int w = 1; w < WINDOW; w++) m = fmaxf(m, s[w]);
        float sum = 0.f;
        #pragma unroll
        for (int w = 0; w < WINDOW; w++) { s[w] = __expf(s[w] - m); sum += s[w]; }
        const float inv = 1.0f / sum;

        // ---- weighted average of window rows ----
        float o0 = 0.f, o1 = 0.f;
        #pragma unroll
        for (int w = 0; w < WINDOW; w++) {
            const float p = s[w] * inv;
            o0 = fmaf(p, xw0[w], o0);
            o1 = fmaf(p, xw1[w], o1);
        }
        out[g * RANK + c0] = o0;
        out[g * RANK + c1] = o1;
    }
}

extern "C" void kernel_launch(void* const* d_in, const int* in_sizes, int n_in,
                              void* d_out, int out_size)
{
    const float* X = (const float*)d_in[0];   // time_factor (L, 64)
    const float* W = (const float*)d_in[1];   // (64, 64)
    const float* b = (const float*)d_in[2];   // (64,)
    float* out = (float*)d_out;               // (L, 64) float32

    const int L    = in_sizes[0] / RANK;
    const int grid = (L + TILE - 1) / TILE;
    attn_win_kernel<<<grid, NTHREADS>>>(X, W, b, out, L);
}

// round 9
// speedup vs baseline: 1.4523x; 1.4523x over previous
#include <cuda_runtime.h>
#include <cuda_bf16.h>

#define RANK     64
#define WINDOW   11
#define PADR     5
#define TILE     64
#define NTHREADS 256
#define NWARPS   8
#define RPW      8                      // rows per warp
#define XROWS    (TILE + 2 * PADR)      // 74
#define WPITCH   76                     // float pitch: lane*19 mod 8 distinct -> conflict-free LDS.128

// Warp-wide fp32 sum, result in all lanes (sm_103 has no redux.f32 -> butterfly).
__device__ __forceinline__ float warp_allreduce_add(float v) {
    #pragma unroll
    for (int o = 16; o > 0; o >>= 1)
        v += __shfl_xor_sync(0xffffffffu, v, o);
    return v;
}

__global__ __launch_bounds__(NTHREADS, 2)
void attn_win_kernel(const float* __restrict__ X,
                     const float* __restrict__ W,
                     const float* __restrict__ bvec,
                     float* __restrict__ out,
                     int L)
{
    __shared__ float xs[XROWS * RANK];     // 18944 B
    __shared__ float ws[RANK * WPITCH];    // 19456 B

    const int tid  = threadIdx.x;
    const int lane = tid & 31;
    const int warp = tid >> 5;
    const int base = blockIdx.x * TILE;

    // ---- stage X tile (zero-padded at edges), coalesced float4 ----
    {
        const float4* X4  = reinterpret_cast<const float4*>(X);
        float4*       xs4 = reinterpret_cast<float4*>(xs);
        #pragma unroll 2
        for (int idx = tid; idx < XROWS * (RANK / 4); idx += NTHREADS) {
            int i  = idx >> 4;
            int ch = idx & 15;
            int g  = base + i - PADR;
            float4 v = make_float4(0.f, 0.f, 0.f, 0.f);
            if (g >= 0 && g < L) v = X4[g * (RANK / 4) + ch];
            xs4[i * (RANK / 4) + ch] = v;
        }
    }
    // ---- stage W into padded-pitch SMEM ----
    {
        const float4* W4 = reinterpret_cast<const float4*>(W);
        for (int idx = tid; idx < RANK * (RANK / 4); idx += NTHREADS) {
            int r  = idx >> 4;
            int ch = idx & 15;
            float4 v = W4[idx];
            *reinterpret_cast<float4*>(&ws[r * WPITCH + ch * 4]) = v;
        }
    }
    __syncthreads();

    const int c0 = lane;
    const int c1 = lane + 32;
    const float bias0 = __ldg(&bvec[c0]);
    const float bias1 = __ldg(&bvec[c1]);

    const int r0 = warp * RPW;             // local row base for this warp

    // ---- batched GEMV for the warp's 8 rows: W read once per K-step for all rows ----
    float acc0[RPW], acc1[RPW];
    #pragma unroll
    for (int r = 0; r < RPW; r++) { acc0[r] = bias0; acc1[r] = bias1; }

    #pragma unroll 4
    for (int j = 0; j < RANK / 4; j++) {
        const float4 a = *reinterpret_cast<const float4*>(&ws[c0 * WPITCH + j * 4]);
        const float4 c = *reinterpret_cast<const float4*>(&ws[c1 * WPITCH + j * 4]);
        #pragma unroll
        for (int r = 0; r < RPW; r++) {
            const float4 xv = *reinterpret_cast<const float4*>(&xs[(r0 + r + PADR) * RANK + j * 4]);
            acc0[r] = fmaf(xv.x, a.x, acc0[r]);
            acc0[r] = fmaf(xv.y, a.y, acc0[r]);
            acc0[r] = fmaf(xv.z, a.z, acc0[r]);
            acc0[r] = fmaf(xv.w, a.w, acc0[r]);
            acc1[r] = fmaf(xv.x, c.x, acc1[r]);
            acc1[r] = fmaf(xv.y, c.y, acc1[r]);
            acc1[r] = fmaf(xv.z, c.z, acc1[r]);
            acc1[r] = fmaf(xv.w, c.w, acc1[r]);
        }
    }
    float v0[RPW], v1[RPW];
    #pragma unroll
    for (int r = 0; r < RPW; r++) {
        v0[r] = tanhf(acc0[r]);
        v1[r] = tanhf(acc1[r]);
    }

    // ---- per-row window scores + softmax + weighted average ----
    #pragma unroll 1
    for (int r = 0; r < RPW; r++) {
        const int lr = r0 + r;
        const int g  = base + lr;
        if (g >= L) break;   // uniform per warp

        float xw0[WINDOW], xw1[WINDOW], s[WINDOW];
        #pragma unroll
        for (int w = 0; w < WINDOW; w++) {
            xw0[w] = xs[(lr + w) * RANK + c0];
            xw1[w] = xs[(lr + w) * RANK + c1];
            const float p = fmaf(xw1[w], v1[r], xw0[w] * v0[r]);
            s[w] = warp_allreduce_add(p) * 0.125f;   // 1/sqrt(RANK)
        }

        float m = s[0];
        #pragma unroll
        for (int w = 1; w < WINDOW; w++) m = fmaxf(m, s[w]);
        float sum = 0.f;
        #pragma unroll
        for (int w = 0; w < WINDOW; w++) { s[w] = __expf(s[w] - m); sum += s[w]; }
        const float inv = 1.0f / sum;

        float o0 = 0.f, o1 = 0.f;
        #pragma unroll
        for (int w = 0; w < WINDOW; w++) {
            const float p = s[w] * inv;
            o0 = fmaf(p, xw0[w], o0);
            o1 = fmaf(p, xw1[w], o1);
        }
        out[g * RANK + c0] = o0;
        out[g * RANK + c1] = o1;
    }
}

extern "C" void kernel_launch(void* const* d_in, const int* in_sizes, int n_in,
                              void* d_out, int out_size)
{
    const float* X = (const float*)d_in[0];   // time_factor (L, 64)
    const float* W = (const float*)d_in[1];   // (64, 64)
    const float* b = (const float*)d_in[2];   // (64,)
    float* out = (float*)d_out;               // (L, 64) float32

    const int L    = in_sizes[0] / RANK;
    const int grid = (L + TILE - 1) / TILE;
    attn_win_kernel<<<grid, NTHREADS>>>(X, W, b, out, L);
}

// round 11
// speedup vs baseline: 2.0148x; 1.3873x over previous
#include <cuda_runtime.h>
#include <cuda_bf16.h>

#define RANK     64
#define WINDOW   11
#define PADR     5
#define TILE     64
#define NTHREADS 256
#define NWARPS   8
#define RPW      8                      // rows per warp
#define XROWS    (TILE + 2 * PADR)      // 74
#define WPITCH   76                     // W pitch: lane*19 mod 8 distinct -> conflict-free LDS.128

__device__ __forceinline__ float tanh_fast(float x) {
    float y;
    asm("tanh.approx.f32 %0, %1;" : "=f"(y) : "f"(x));
    return y;
}

__global__ __launch_bounds__(NTHREADS, 2)
void attn_win_kernel(const float* __restrict__ X,
                     const float* __restrict__ W,
                     const float* __restrict__ bvec,
                     float* __restrict__ out,
                     int L)
{
    __shared__ float xs[XROWS * RANK];     // 18944 B
    __shared__ float wv[RANK * WPITCH];    // 19456 B: holds W (pitch 76), later reused for V (pitch 64)

    const int tid  = threadIdx.x;
    const int lane = tid & 31;
    const int warp = tid >> 5;
    const int base = blockIdx.x * TILE;

    // ---- stage X tile (zero-padded at edges), coalesced float4 ----
    {
        const float4* X4  = reinterpret_cast<const float4*>(X);
        float4*       xs4 = reinterpret_cast<float4*>(xs);
        #pragma unroll 2
        for (int idx = tid; idx < XROWS * (RANK / 4); idx += NTHREADS) {
            int i  = idx >> 4;
            int ch = idx & 15;
            int g  = base + i - PADR;
            float4 v = make_float4(0.f, 0.f, 0.f, 0.f);
            if (g >= 0 && g < L) v = X4[g * (RANK / 4) + ch];
            xs4[i * (RANK / 4) + ch] = v;
        }
    }
    // ---- stage W into padded-pitch SMEM ----
    {
        const float4* W4 = reinterpret_cast<const float4*>(W);
        for (int idx = tid; idx < RANK * (RANK / 4); idx += NTHREADS) {
            int r  = idx >> 4;
            int ch = idx & 15;
            float4 v = W4[idx];
            *reinterpret_cast<float4*>(&wv[r * WPITCH + ch * 4]) = v;
        }
    }
    __syncthreads();

    const int c0 = lane;
    const int c1 = lane + 32;
    const float bias0 = bvec[c0];
    const float bias1 = bvec[c1];
    const int r0 = warp * RPW;             // local row base for this warp

    // ---- batched GEMV for the warp's 8 rows: W read once per K-step for all rows ----
    float acc0[RPW], acc1[RPW];
    #pragma unroll
    for (int r = 0; r < RPW; r++) { acc0[r] = bias0; acc1[r] = bias1; }

    #pragma unroll 4
    for (int j = 0; j < RANK / 4; j++) {
        const float4 a = *reinterpret_cast<const float4*>(&wv[c0 * WPITCH + j * 4]);
        const float4 c = *reinterpret_cast<const float4*>(&wv[c1 * WPITCH + j * 4]);
        #pragma unroll
        for (int r = 0; r < RPW; r++) {
            const float4 xv = *reinterpret_cast<const float4*>(&xs[(r0 + r + PADR) * RANK + j * 4]);
            acc0[r] = fmaf(xv.x, a.x, acc0[r]);
            acc0[r] = fmaf(xv.y, a.y, acc0[r]);
            acc0[r] = fmaf(xv.z, a.z, acc0[r]);
            acc0[r] = fmaf(xv.w, a.w, acc0[r]);
            acc1[r] = fmaf(xv.x, c.x, acc1[r]);
            acc1[r] = fmaf(xv.y, c.y, acc1[r]);
            acc1[r] = fmaf(xv.z, c.z, acc1[r]);
            acc1[r] = fmaf(xv.w, c.w, acc1[r]);
        }
    }
    float v0[RPW], v1[RPW];
    #pragma unroll
    for (int r = 0; r < RPW; r++) {
        v0[r] = tanh_fast(acc0[r]);
        v1[r] = tanh_fast(acc1[r]);
    }

    __syncthreads();   // all warps finished reading W -> wv reusable as V

    // ---- stash V (pitch 64) into the dead W buffer; rows are warp-private ----
    #pragma unroll
    for (int r = 0; r < RPW; r++) {
        wv[(r0 + r) * RANK + c0] = v0[r];
        wv[(r0 + r) * RANK + c1] = v1[r];
    }
    __syncwarp();

    // ---- group-of-8 layout: 4 groups/warp, group owns one row, lane owns 8 channels ----
    const int grp = lane >> 3;            // 0..3
    const int cA  = (lane & 7) * 4;       // quarter-warp reads 128B contiguous -> conflict-free
    const int cB  = cA + 32;

    #pragma unroll
    for (int b = 0; b < 2; b++) {
        const int lrow = r0 + b * 4 + grp;        // local row 0..63
        const float4 va = *reinterpret_cast<const float4*>(&wv[lrow * RANK + cA]);
        const float4 vb = *reinterpret_cast<const float4*>(&wv[lrow * RANK + cB]);

        // scores: s[w] = <x[lrow+w-5], v> / 8   (3-stage butterfly within 8 lanes)
        float s[WINDOW];
        #pragma unroll
        for (int w = 0; w < WINDOW; w++) {
            const float4 xa = *reinterpret_cast<const float4*>(&xs[(lrow + w) * RANK + cA]);
            const float4 xb = *reinterpret_cast<const float4*>(&xs[(lrow + w) * RANK + cB]);
            float p = xa.x * va.x;
            p = fmaf(xa.y, va.y, p);
            p = fmaf(xa.z, va.z, p);
            p = fmaf(xa.w, va.w, p);
            p = fmaf(xb.x, vb.x, p);
            p = fmaf(xb.y, vb.y, p);
            p = fmaf(xb.z, vb.z, p);
            p = fmaf(xb.w, vb.w, p);
            p += __shfl_xor_sync(0xffffffffu, p, 4);
            p += __shfl_xor_sync(0xffffffffu, p, 2);
            p += __shfl_xor_sync(0xffffffffu, p, 1);
            s[w] = p * 0.125f;   // 1/sqrt(RANK)
        }

        // softmax over the window (replicated in-group, register-local)
        float m = s[0];
        #pragma unroll
        for (int w = 1; w < WINDOW; w++) m = fmaxf(m, s[w]);
        float sum = 0.f;
        #pragma unroll
        for (int w = 0; w < WINDOW; w++) { s[w] = __expf(s[w] - m); sum += s[w]; }
        const float inv = 1.0f / sum;
        #pragma unroll
        for (int w = 0; w < WINDOW; w++) s[w] *= inv;

        // weighted average of window rows (no reduction; 8 channels per lane)
        float4 oa = make_float4(0.f, 0.f, 0.f, 0.f);
        float4 ob = make_float4(0.f, 0.f, 0.f, 0.f);
        #pragma unroll
        for (int w = 0; w < WINDOW; w++) {
            const float4 xa = *reinterpret_cast<const float4*>(&xs[(lrow + w) * RANK + cA]);
            const float4 xb = *reinterpret_cast<const float4*>(&xs[(lrow + w) * RANK + cB]);
            const float pw = s[w];
            oa.x = fmaf(pw, xa.x, oa.x);
            oa.y = fmaf(pw, xa.y, oa.y);
            oa.z = fmaf(pw, xa.z, oa.z);
            oa.w = fmaf(pw, xa.w, oa.w);
            ob.x = fmaf(pw, xb.x, ob.x);
            ob.y = fmaf(pw, xb.y, ob.y);
            ob.z = fmaf(pw, xb.z, ob.z);
            ob.w = fmaf(pw, xb.w, ob.w);
        }
        const int g = base + lrow;
        if (g < L) {
            *reinterpret_cast<float4*>(&out[g * RANK + cA]) = oa;
            *reinterpret_cast<float4*>(&out[g * RANK + cB]) = ob;
        }
    }
}

extern "C" void kernel_launch(void* const* d_in, const int* in_sizes, int n_in,
                              void* d_out, int out_size)
{
    const float* X = (const float*)d_in[0];   // time_factor (L, 64)
    const float* W = (const float*)d_in[1];   // (64, 64)
    const float* b = (const float*)d_in[2];   // (64,)
    float* out = (float*)d_out;               // (L, 64) float32

    const int L    = in_sizes[0] / RANK;
    const int grid = (L + TILE - 1) / TILE;
    attn_win_kernel<<<grid, NTHREADS>>>(X, W, b, out, L);
}

// round 14
// speedup vs baseline: 2.2911x; 1.1372x over previous
#include <cuda_runtime.h>
#include <cuda_bf16.h>

#define RANK     64
#define WINDOW   11
#define PADR     5
#define TILE     64
#define NTHREADS 256
#define NWARPS   8
#define RPW      8                      // rows per warp
#define XROWS    (TILE + 2 * PADR)      // 74
#define WPITCH   76                     // W pitch: lane*19 mod 8 distinct -> conflict-free LDS.128

__device__ __forceinline__ float tanh_fast(float x) {
    float y;
    asm("tanh.approx.f32 %0, %1;" : "=f"(y) : "f"(x));
    return y;
}

__global__ __launch_bounds__(NTHREADS, 3)
void attn_win_kernel(const float* __restrict__ X,
                     const float* __restrict__ W,
                     const float* __restrict__ bvec,
                     float* __restrict__ out,
                     int L)
{
    __shared__ float xs[XROWS * RANK];     // 18944 B
    __shared__ float wv[RANK * WPITCH];    // 19456 B: W (pitch 76), later reused for V (pitch 64)

    const int tid  = threadIdx.x;
    const int lane = tid & 31;
    const int warp = tid >> 5;
    const int base = blockIdx.x * TILE;

    // ---- stage X tile (zero-padded at edges), coalesced float4 ----
    {
        const float4* X4  = reinterpret_cast<const float4*>(X);
        float4*       xs4 = reinterpret_cast<float4*>(xs);
        #pragma unroll 2
        for (int idx = tid; idx < XROWS * (RANK / 4); idx += NTHREADS) {
            int i  = idx >> 4;
            int ch = idx & 15;
            int g  = base + i - PADR;
            float4 v = make_float4(0.f, 0.f, 0.f, 0.f);
            if (g >= 0 && g < L) v = X4[g * (RANK / 4) + ch];
            xs4[i * (RANK / 4) + ch] = v;
        }
    }
    // ---- stage W into padded-pitch SMEM ----
    {
        const float4* W4 = reinterpret_cast<const float4*>(W);
        for (int idx = tid; idx < RANK * (RANK / 4); idx += NTHREADS) {
            int r  = idx >> 4;
            int ch = idx & 15;
            float4 v = W4[idx];
            *reinterpret_cast<float4*>(&wv[r * WPITCH + ch * 4]) = v;
        }
    }
    __syncthreads();

    const int c0 = lane;
    const int c1 = lane + 32;
    const float bias0 = bvec[c0];
    const float bias1 = bvec[c1];
    const int r0 = warp * RPW;             // local row base for this warp

    // ---- batched GEMV for the warp's 8 rows: W read once per K-step for all rows ----
    float acc0[RPW], acc1[RPW];
    #pragma unroll
    for (int r = 0; r < RPW; r++) { acc0[r] = bias0; acc1[r] = bias1; }

    #pragma unroll 4
    for (int j = 0; j < RANK / 4; j++) {
        const float4 a = *reinterpret_cast<const float4*>(&wv[c0 * WPITCH + j * 4]);
        const float4 c = *reinterpret_cast<const float4*>(&wv[c1 * WPITCH + j * 4]);
        #pragma unroll
        for (int r = 0; r < RPW; r++) {
            const float4 xv = *reinterpret_cast<const float4*>(&xs[(r0 + r + PADR) * RANK + j * 4]);
            acc0[r] = fmaf(xv.x, a.x, acc0[r]);
            acc0[r] = fmaf(xv.y, a.y, acc0[r]);
            acc0[r] = fmaf(xv.z, a.z, acc0[r]);
            acc0[r] = fmaf(xv.w, a.w, acc0[r]);
            acc1[r] = fmaf(xv.x, c.x, acc1[r]);
            acc1[r] = fmaf(xv.y, c.y, acc1[r]);
            acc1[r] = fmaf(xv.z, c.z, acc1[r]);
            acc1[r] = fmaf(xv.w, c.w, acc1[r]);
        }
    }

    __syncthreads();   // all warps done reading W -> wv reusable as V

    // ---- stash V = tanh(acc) (pitch 64) into the dead W buffer ----
    #pragma unroll
    for (int r = 0; r < RPW; r++) {
        wv[(r0 + r) * RANK + c0] = tanh_fast(acc0[r]);
        wv[(r0 + r) * RANK + c1] = tanh_fast(acc1[r]);
    }
    __syncwarp();

    // ---- group-of-8 layout: 4 groups/warp, group owns one row, lane owns 8 channels ----
    const int grp = lane >> 3;            // 0..3
    const int cA  = (lane & 7) * 4;       // quarter-warp reads 128B contiguous -> conflict-free
    const int cB  = cA + 32;

    #pragma unroll
    for (int b = 0; b < 2; b++) {
        const int lrow = r0 + b * 4 + grp;        // local row 0..63
        const float4 va = *reinterpret_cast<const float4*>(&wv[lrow * RANK + cA]);
        const float4 vb = *reinterpret_cast<const float4*>(&wv[lrow * RANK + cB]);

        // single-pass softmax-weighted average (scores bounded ~|s|<5 -> no max needed)
        float4 oa = make_float4(0.f, 0.f, 0.f, 0.f);
        float4 ob = make_float4(0.f, 0.f, 0.f, 0.f);
        float sum = 0.f;
        #pragma unroll
        for (int w = 0; w < WINDOW; w++) {
            const float4 xa = *reinterpret_cast<const float4*>(&xs[(lrow + w) * RANK + cA]);
            const float4 xb = *reinterpret_cast<const float4*>(&xs[(lrow + w) * RANK + cB]);
            float p = xa.x * va.x;
            p = fmaf(xa.y, va.y, p);
            p = fmaf(xa.z, va.z, p);
            p = fmaf(xa.w, va.w, p);
            p = fmaf(xb.x, vb.x, p);
            p = fmaf(xb.y, vb.y, p);
            p = fmaf(xb.z, vb.z, p);
            p = fmaf(xb.w, vb.w, p);
            p += __shfl_xor_sync(0xffffffffu, p, 4);
            p += __shfl_xor_sync(0xffffffffu, p, 2);
            p += __shfl_xor_sync(0xffffffffu, p, 1);
            const float e = __expf(p * 0.125f);   // 1/sqrt(RANK)
            sum += e;
            oa.x = fmaf(e, xa.x, oa.x);
            oa.y = fmaf(e, xa.y, oa.y);
            oa.z = fmaf(e, xa.z, oa.z);
            oa.w = fmaf(e, xa.w, oa.w);
            ob.x = fmaf(e, xb.x, ob.x);
            ob.y = fmaf(e, xb.y, ob.y);
            ob.z = fmaf(e, xb.z, ob.z);
            ob.w = fmaf(e, xb.w, ob.w);
        }
        const float inv = 1.0f / sum;
        oa.x *= inv; oa.y *= inv; oa.z *= inv; oa.w *= inv;
        ob.x *= inv; ob.y *= inv; ob.z *= inv; ob.w *= inv;

        const int g = base + lrow;
        if (g < L) {
            *reinterpret_cast<float4*>(&out[g * RANK + cA]) = oa;
            *reinterpret_cast<float4*>(&out[g * RANK + cB]) = ob;
        }
    }
}

extern "C" void kernel_launch(void* const* d_in, const int* in_sizes, int n_in,
                              void* d_out, int out_size)
{
    const float* X = (const float*)d_in[0];   // time_factor (L, 64)
    const float* W = (const float*)d_in[1];   // (64, 64)
    const float* b = (const float*)d_in[2];   // (64,)
    float* out = (float*)d_out;               // (L, 64) float32

    const int L    = in_sizes[0] / RANK;
    const int grid = (L + TILE - 1) / TILE;
    attn_win_kernel<<<grid, NTHREADS>>>(X, W, b, out, L);
}